// round 5
// baseline (speedup 1.0000x reference)
#include <cuda_runtime.h>
#include <cuda_fp16.h>
#include <cstdint>
#include <cstddef>

// ============================================================
// out[16384,4096] = X[16384,4096] @ W[4096,4096]^T
// W = (w_pos>0) - (w_neg>0)  in {-1,0,+1}  (exact in fp16)
// CTA 128x256xK64, 8 warps (2x4), warp tile 64x64, 4-stage cp.async,
// register double-buffered fragments; swizzle hoisted with XOR k-step offset
// ============================================================
#define M_TOTAL 16384
#define N_TOTAL 4096
#define K_TOTAL 4096

#define TILE_M 128
#define TILE_N 256
#define TILE_K 64
#define STAGES 4
#define NCHUNK (K_TOTAL / TILE_K)         // 64
#define N_TILES (N_TOTAL / TILE_N)        // 16
#define M_TILES (M_TOTAL / TILE_M)        // 128

#define A_BYTES (TILE_M * TILE_K * 2)     // 16384
#define B_BYTES (TILE_N * TILE_K * 2)     // 32768
#define STAGE_BYTES (A_BYTES + B_BYTES)   // 49152
#define SMEM_TOTAL (STAGES * STAGE_BYTES) // 196608

__device__ __align__(128) __half g_W[(size_t)N_TOTAL * K_TOTAL];  // [N,K] 32 MB
__device__ __align__(128) __half g_X[(size_t)M_TOTAL * K_TOTAL];  // [M,K] 128 MB

// ============================================================
// Base-ISA PTX helpers
// ============================================================
__device__ __forceinline__ uint32_t smem_u32(const void* p) {
    uint32_t a;
    asm("{ .reg .u64 t; cvta.to.shared.u64 t, %1; cvt.u32.u64 %0, t; }"
        : "=r"(a) : "l"(p));
    return a;
}

#define CP_ASYNC16(dst_u32, src_ptr) \
    asm volatile("cp.async.cg.shared.global [%0], [%1], 16;" \
                 :: "r"(dst_u32), "l"(src_ptr) : "memory")
#define CP_COMMIT() asm volatile("cp.async.commit_group;" ::: "memory")
#define CP_WAIT(n)  asm volatile("cp.async.wait_group %0;" :: "n"(n) : "memory")

__device__ __forceinline__ void ldsm4(uint32_t* r, uint32_t addr) {
    asm volatile("ldmatrix.sync.aligned.m8n8.x4.shared.b16 {%0,%1,%2,%3}, [%4];"
                 : "=r"(r[0]), "=r"(r[1]), "=r"(r[2]), "=r"(r[3]) : "r"(addr));
}

__device__ __forceinline__ void mma16816(float* d, const uint32_t* a,
                                         uint32_t b0, uint32_t b1) {
    asm volatile(
        "mma.sync.aligned.m16n8k16.row.col.f32.f16.f16.f32 "
        "{%0,%1,%2,%3}, {%4,%5,%6,%7}, {%8,%9}, {%0,%1,%2,%3};"
        : "+f"(d[0]), "+f"(d[1]), "+f"(d[2]), "+f"(d[3])
        : "r"(a[0]), "r"(a[1]), "r"(a[2]), "r"(a[3]), "r"(b0), "r"(b1));
}

__device__ __forceinline__ uint32_t sw128(uint32_t off) {
    return off ^ ((off >> 3) & 0x70u);
}

// ============================================================
// Prep kernels
// ============================================================
__global__ void k_cvt_x(const float4* __restrict__ x, int n4) {
    int i = blockIdx.x * blockDim.x + threadIdx.x;
    if (i < n4) {
        float4 v = x[i];
        __half2* dst = (__half2*)g_X;
        dst[2 * i + 0] = __floats2half2_rn(v.x, v.y);
        dst[2 * i + 1] = __floats2half2_rn(v.z, v.w);
    }
}

__global__ void k_binarize_w(const float4* __restrict__ wp,
                             const float4* __restrict__ wn, int n4) {
    int i = blockIdx.x * blockDim.x + threadIdx.x;
    if (i < n4) {
        float4 p = wp[i];
        float4 n = wn[i];
        float a = (float)((p.x > 0.f) - (n.x > 0.f));
        float b = (float)((p.y > 0.f) - (n.y > 0.f));
        float c = (float)((p.z > 0.f) - (n.z > 0.f));
        float d = (float)((p.w > 0.f) - (n.w > 0.f));
        __half2* dst = (__half2*)g_W;
        dst[2 * i + 0] = __floats2half2_rn(a, b);
        dst[2 * i + 1] = __floats2half2_rn(c, d);
    }
}

// ============================================================
// GEMM
// ============================================================
__device__ __forceinline__ void issue_tile_loads(
    uint32_t smem_base, int s, int kc, int m0, int n0, int tid)
{
    uint32_t sa = smem_base + (uint32_t)s * STAGE_BYTES;
    uint32_t sb = sa + A_BYTES;
    const int row = tid >> 1;
    const int c0  = (tid & 1) * 4;
    const char* srcA = (const char*)(g_X + (size_t)(m0 + row) * K_TOTAL + kc * TILE_K);
    uint32_t rb = (uint32_t)row * 128u;
    #pragma unroll
    for (int c = 0; c < 4; c++) {
        uint32_t off = rb + (uint32_t)(c0 + c) * 16u;
        CP_ASYNC16(sa + sw128(off), srcA + (c0 + c) * 16);
    }
    #pragma unroll
    for (int rr = 0; rr < 2; rr++) {
        const int brow = row + rr * 128;
        const char* srcB = (const char*)(g_W + (size_t)(n0 + brow) * K_TOTAL + kc * TILE_K);
        uint32_t bb = (uint32_t)brow * 128u;
        #pragma unroll
        for (int c = 0; c < 4; c++) {
            uint32_t off = bb + (uint32_t)(c0 + c) * 16u;
            CP_ASYNC16(sb + sw128(off), srcB + (c0 + c) * 16);
        }
    }
}

__global__ void __launch_bounds__(256, 1) plinear_gemm(float* __restrict__ out) {
    extern __shared__ char smem[];
    uint32_t smem_base = smem_u32(smem);
    const int tid = threadIdx.x;
    const int wid = tid >> 5;
    const int lid = tid & 31;

    // N-fast: a wave shares X tiles, W stays L2-resident
    const int nt = blockIdx.x & (N_TILES - 1);
    const int mt = blockIdx.x >> 4;
    const int m0 = mt * TILE_M;
    const int n0 = nt * TILE_N;

    // warp grid 2(M) x 4(N): warp tile 64 x 64
    const int mwarp = (wid >> 2) * 64;
    const int nwarp = (wid & 3) * 64;

    float acc[4][8][4];
    #pragma unroll
    for (int i = 0; i < 4; i++)
        #pragma unroll
        for (int j = 0; j < 8; j++)
            #pragma unroll
            for (int c = 0; c < 4; c++) acc[i][j][c] = 0.f;

    // Pre-swizzled ldmatrix base offsets. k-step advance: column bits 5-6 of
    // the PRE-swizzle offset are zero, so off+kb == off^kb and the swizzle
    // XOR commutes: sw128(off+kb) == sw128(off) ^ kb. (The '+' form carries
    // into bit 7 and faults — R4 bug.)
    const int a_r = (lid & 7) + (((lid >> 3) & 1) << 3);
    const int a_c = (lid >> 4) << 4;
    const int b_r = (lid & 7) + ((lid >> 4) << 3);
    const int b_c = ((lid >> 3) & 1) << 4;
    uint32_t aoff[4], boff[4];
    #pragma unroll
    for (int i = 0; i < 4; i++)
        aoff[i] = sw128((uint32_t)(mwarp + i * 16 + a_r) * 128u + a_c);
    #pragma unroll
    for (int j = 0; j < 4; j++)
        boff[j] = sw128((uint32_t)(nwarp + j * 16 + b_r) * 128u + b_c) + A_BYTES;

    // Prologue: stages 0..2
    issue_tile_loads(smem_base, 0, 0, m0, n0, tid); CP_COMMIT();
    issue_tile_loads(smem_base, 1, 1, m0, n0, tid); CP_COMMIT();
    issue_tile_loads(smem_base, 2, 2, m0, n0, tid); CP_COMMIT();

    uint32_t a[2][4][4], b[2][4][4];

    #pragma unroll 1
    for (int kc = 0; kc < NCHUNK; kc++) {
        CP_WAIT(2);          // stage kc ready
        __syncthreads();     // + stage kc-1 reads complete

        const int pf = kc + 3;
        if (pf < NCHUNK)
            issue_tile_loads(smem_base, pf & (STAGES - 1), pf, m0, n0, tid);
        CP_COMMIT();

        const uint32_t sa = smem_base + (uint32_t)(kc & (STAGES - 1)) * STAGE_BYTES;

        // Load k-step 0 fragments
        #pragma unroll
        for (int i = 0; i < 4; i++) ldsm4(a[0][i], sa + aoff[i]);
        #pragma unroll
        for (int j = 0; j < 4; j++) ldsm4(b[0][j], sa + boff[j]);

        #pragma unroll
        for (int ks = 0; ks < 4; ks++) {
            const int cur = ks & 1, nxt = cur ^ 1;
            if (ks < 3) {
                const uint32_t kb = (uint32_t)(ks + 1) * 32u;  // bits 5-6 only
                #pragma unroll
                for (int i = 0; i < 4; i++) ldsm4(a[nxt][i], sa + (aoff[i] ^ kb));
                #pragma unroll
                for (int j = 0; j < 4; j++) ldsm4(b[nxt][j], sa + (boff[j] ^ kb));
            }
            #pragma unroll
            for (int i = 0; i < 4; i++)
                #pragma unroll
                for (int j = 0; j < 4; j++) {
                    mma16816(acc[i][2 * j + 0], a[cur][i], b[cur][j][0], b[cur][j][1]);
                    mma16816(acc[i][2 * j + 1], a[cur][i], b[cur][j][2], b[cur][j][3]);
                }
        }
    }

    // Epilogue
    {
        const int g  = lid >> 2;
        const int t2 = (lid & 3) * 2;
        #pragma unroll
        for (int i = 0; i < 4; i++) {
            float* r0 = out + (size_t)(m0 + mwarp + i * 16 + g) * N_TOTAL + n0 + nwarp + t2;
            float* r1 = r0 + 8 * N_TOTAL;
            #pragma unroll
            for (int j = 0; j < 8; j++) {
                *(float2*)(r0 + j * 8) = make_float2(acc[i][j][0], acc[i][j][1]);
                *(float2*)(r1 + j * 8) = make_float2(acc[i][j][2], acc[i][j][3]);
            }
        }
    }
}

// ============================================================
// Launch
// ============================================================
extern "C" void kernel_launch(void* const* d_in, const int* in_sizes, int n_in,
                              void* d_out, int out_size) {
    const float* x  = (const float*)d_in[0];
    const float* wp = (const float*)d_in[1];
    const float* wn = (const float*)d_in[2];
    float* out = (float*)d_out;

    cudaFuncSetAttribute(plinear_gemm,
                         cudaFuncAttributeMaxDynamicSharedMemorySize, SMEM_TOTAL);

    const int n4x = (M_TOTAL * K_TOTAL) / 4;
    const int n4w = (N_TOTAL * K_TOTAL) / 4;
    k_cvt_x<<<n4x / 256, 256>>>((const float4*)x, n4x);
    k_binarize_w<<<n4w / 256, 256>>>((const float4*)wp, (const float4*)wn, n4w);

    plinear_gemm<<<M_TILES * N_TILES, 256, SMEM_TOTAL>>>(out);
}

// round 6
// speedup vs baseline: 1.0458x; 1.0458x over previous
#include <cuda_runtime.h>
#include <cuda_fp16.h>
#include <cstdint>
#include <cstddef>

// ============================================================
// out[16384,4096] = X[16384,4096] @ W[4096,4096]^T
// W = (w_pos>0) - (w_neg>0)  in {-1,0,+1}  (exact in fp16)
// CTA 128x256xK64, 16 warps (2x8), warp tile 64x32, 4-stage cp.async,
// register double-buffered fragments, XOR k-step swizzle advance.
// ============================================================
#define M_TOTAL 16384
#define N_TOTAL 4096
#define K_TOTAL 4096

#define TILE_M 128
#define TILE_N 256
#define TILE_K 64
#define STAGES 4
#define NCHUNK (K_TOTAL / TILE_K)         // 64
#define N_TILES (N_TOTAL / TILE_N)        // 16
#define M_TILES (M_TOTAL / TILE_M)        // 128

#define A_BYTES (TILE_M * TILE_K * 2)     // 16384
#define B_BYTES (TILE_N * TILE_K * 2)     // 32768
#define STAGE_BYTES (A_BYTES + B_BYTES)   // 49152
#define SMEM_TOTAL (STAGES * STAGE_BYTES) // 196608

__device__ __align__(128) __half g_W[(size_t)N_TOTAL * K_TOTAL];  // [N,K] 32 MB
__device__ __align__(128) __half g_X[(size_t)M_TOTAL * K_TOTAL];  // [M,K] 128 MB

// ============================================================
// Base-ISA PTX helpers
// ============================================================
__device__ __forceinline__ uint32_t smem_u32(const void* p) {
    uint32_t a;
    asm("{ .reg .u64 t; cvta.to.shared.u64 t, %1; cvt.u32.u64 %0, t; }"
        : "=r"(a) : "l"(p));
    return a;
}

#define CP_ASYNC16(dst_u32, src_ptr) \
    asm volatile("cp.async.cg.shared.global [%0], [%1], 16;" \
                 :: "r"(dst_u32), "l"(src_ptr) : "memory")
#define CP_COMMIT() asm volatile("cp.async.commit_group;" ::: "memory")
#define CP_WAIT(n)  asm volatile("cp.async.wait_group %0;" :: "n"(n) : "memory")

__device__ __forceinline__ void ldsm4(uint32_t* r, uint32_t addr) {
    asm volatile("ldmatrix.sync.aligned.m8n8.x4.shared.b16 {%0,%1,%2,%3}, [%4];"
                 : "=r"(r[0]), "=r"(r[1]), "=r"(r[2]), "=r"(r[3]) : "r"(addr));
}

__device__ __forceinline__ void mma16816(float* d, const uint32_t* a,
                                         uint32_t b0, uint32_t b1) {
    asm volatile(
        "mma.sync.aligned.m16n8k16.row.col.f32.f16.f16.f32 "
        "{%0,%1,%2,%3}, {%4,%5,%6,%7}, {%8,%9}, {%0,%1,%2,%3};"
        : "+f"(d[0]), "+f"(d[1]), "+f"(d[2]), "+f"(d[3])
        : "r"(a[0]), "r"(a[1]), "r"(a[2]), "r"(a[3]), "r"(b0), "r"(b1));
}

__device__ __forceinline__ uint32_t sw128(uint32_t off) {
    return off ^ ((off >> 3) & 0x70u);
}

// ============================================================
// Merged prep kernel (one launch: fixes ncu -s alignment, saves overhead)
// blocks [0, XB): convert x -> fp16 ; blocks [XB, XB+WB): binarize w
// ============================================================
#define N4X ((M_TOTAL * K_TOTAL) / 4)     // 16777216
#define N4W ((N_TOTAL * K_TOTAL) / 4)     // 4194304
#define XB  (N4X / 256)                   // 65536 blocks
#define WB  (N4W / 256)                   // 16384 blocks

__global__ void k_prep(const float4* __restrict__ x,
                       const float4* __restrict__ wp,
                       const float4* __restrict__ wn) {
    int i = blockIdx.x * 256 + threadIdx.x;
    if (i < N4X) {
        float4 v = x[i];
        __half2* dst = (__half2*)g_X;
        dst[2 * i + 0] = __floats2half2_rn(v.x, v.y);
        dst[2 * i + 1] = __floats2half2_rn(v.z, v.w);
    } else {
        int j = i - N4X;
        float4 p = wp[j];
        float4 n = wn[j];
        float a = (float)((p.x > 0.f) - (n.x > 0.f));
        float b = (float)((p.y > 0.f) - (n.y > 0.f));
        float c = (float)((p.z > 0.f) - (n.z > 0.f));
        float d = (float)((p.w > 0.f) - (n.w > 0.f));
        __half2* dst = (__half2*)g_W;
        dst[2 * j + 0] = __floats2half2_rn(a, b);
        dst[2 * j + 1] = __floats2half2_rn(c, d);
    }
}

// ============================================================
// GEMM
// ============================================================
// Stage fill with 512 threads: A (16KB): thread t -> row t>>2, 2x16B at
// col (t&3)*32. B (32KB): thread t -> row t>>1, 4x16B at col (t&1)*64.
__device__ __forceinline__ void issue_tile_loads(
    uint32_t smem_base, int s, int kc, int m0, int n0, int tid)
{
    uint32_t sa = smem_base + (uint32_t)s * STAGE_BYTES;
    uint32_t sb = sa + A_BYTES;
    {
        const int row = tid >> 2;
        const int c0  = (tid & 3) * 2;
        const char* srcA = (const char*)(g_X + (size_t)(m0 + row) * K_TOTAL + kc * TILE_K);
        uint32_t rb = (uint32_t)row * 128u;
        #pragma unroll
        for (int c = 0; c < 2; c++) {
            uint32_t off = rb + (uint32_t)(c0 + c) * 16u;
            CP_ASYNC16(sa + sw128(off), srcA + (c0 + c) * 16);
        }
    }
    {
        const int row = tid >> 1;
        const int c0  = (tid & 1) * 4;
        const char* srcB = (const char*)(g_W + (size_t)(n0 + row) * K_TOTAL + kc * TILE_K);
        uint32_t rb = (uint32_t)row * 128u;
        #pragma unroll
        for (int c = 0; c < 4; c++) {
            uint32_t off = rb + (uint32_t)(c0 + c) * 16u;
            CP_ASYNC16(sb + sw128(off), srcB + (c0 + c) * 16);
        }
    }
}

__global__ void __launch_bounds__(512, 1) plinear_gemm(float* __restrict__ out) {
    extern __shared__ char smem[];
    uint32_t smem_base = smem_u32(smem);
    const int tid = threadIdx.x;
    const int wid = tid >> 5;
    const int lid = tid & 31;

    // N-fast: a wave shares X tiles, W stays L2-resident
    const int nt = blockIdx.x & (N_TILES - 1);
    const int mt = blockIdx.x >> 4;
    const int m0 = mt * TILE_M;
    const int n0 = nt * TILE_N;

    // warp grid 2(M) x 8(N): warp tile 64 x 32
    const int mwarp = (wid >> 3) * 64;
    const int nwarp = (wid & 7) * 32;

    float acc[4][4][4];
    #pragma unroll
    for (int i = 0; i < 4; i++)
        #pragma unroll
        for (int j = 0; j < 4; j++)
            #pragma unroll
            for (int c = 0; c < 4; c++) acc[i][j][c] = 0.f;

    // Pre-swizzled ldmatrix base offsets; k-step advance by XOR (col bits 5-6
    // of the pre-swizzle offset are zero -> sw128(off+kb) == sw128(off)^kb).
    const int a_r = (lid & 7) + (((lid >> 3) & 1) << 3);
    const int a_c = (lid >> 4) << 4;
    const int b_r = (lid & 7) + ((lid >> 4) << 3);
    const int b_c = ((lid >> 3) & 1) << 4;
    uint32_t aoff[4], boff[2];
    #pragma unroll
    for (int i = 0; i < 4; i++)
        aoff[i] = sw128((uint32_t)(mwarp + i * 16 + a_r) * 128u + a_c);
    #pragma unroll
    for (int j = 0; j < 2; j++)
        boff[j] = sw128((uint32_t)(nwarp + j * 16 + b_r) * 128u + b_c) + A_BYTES;

    // Prologue: stages 0..2
    issue_tile_loads(smem_base, 0, 0, m0, n0, tid); CP_COMMIT();
    issue_tile_loads(smem_base, 1, 1, m0, n0, tid); CP_COMMIT();
    issue_tile_loads(smem_base, 2, 2, m0, n0, tid); CP_COMMIT();

    uint32_t a[2][4][4], b[2][2][4];

    #pragma unroll 1
    for (int kc = 0; kc < NCHUNK; kc++) {
        CP_WAIT(2);          // stage kc ready
        __syncthreads();     // + stage kc-1 reads complete

        const int pf = kc + 3;
        if (pf < NCHUNK)
            issue_tile_loads(smem_base, pf & (STAGES - 1), pf, m0, n0, tid);
        CP_COMMIT();

        const uint32_t sa = smem_base + (uint32_t)(kc & (STAGES - 1)) * STAGE_BYTES;

        // k-step 0 fragments
        #pragma unroll
        for (int i = 0; i < 4; i++) ldsm4(a[0][i], sa + aoff[i]);
        #pragma unroll
        for (int j = 0; j < 2; j++) ldsm4(b[0][j], sa + boff[j]);

        #pragma unroll
        for (int ks = 0; ks < 4; ks++) {
            const int cur = ks & 1, nxt = cur ^ 1;
            if (ks < 3) {
                const uint32_t kb = (uint32_t)(ks + 1) * 32u;  // bits 5-6 only
                #pragma unroll
                for (int i = 0; i < 4; i++) ldsm4(a[nxt][i], sa + (aoff[i] ^ kb));
                #pragma unroll
                for (int j = 0; j < 2; j++) ldsm4(b[nxt][j], sa + (boff[j] ^ kb));
            }
            #pragma unroll
            for (int i = 0; i < 4; i++)
                #pragma unroll
                for (int j = 0; j < 2; j++) {
                    mma16816(acc[i][2 * j + 0], a[cur][i], b[cur][j][0], b[cur][j][1]);
                    mma16816(acc[i][2 * j + 1], a[cur][i], b[cur][j][2], b[cur][j][3]);
                }
        }
    }

    // Epilogue
    {
        const int g  = lid >> 2;
        const int t2 = (lid & 3) * 2;
        #pragma unroll
        for (int i = 0; i < 4; i++) {
            float* r0 = out + (size_t)(m0 + mwarp + i * 16 + g) * N_TOTAL + n0 + nwarp + t2;
            float* r1 = r0 + 8 * N_TOTAL;
            #pragma unroll
            for (int j = 0; j < 4; j++) {
                *(float2*)(r0 + j * 8) = make_float2(acc[i][j][0], acc[i][j][1]);
                *(float2*)(r1 + j * 8) = make_float2(acc[i][j][2], acc[i][j][3]);
            }
        }
    }
}

// ============================================================
// Launch
// ============================================================
extern "C" void kernel_launch(void* const* d_in, const int* in_sizes, int n_in,
                              void* d_out, int out_size) {
    const float* x  = (const float*)d_in[0];
    const float* wp = (const float*)d_in[1];
    const float* wn = (const float*)d_in[2];
    float* out = (float*)d_out;

    cudaFuncSetAttribute(plinear_gemm,
                         cudaFuncAttributeMaxDynamicSharedMemorySize, SMEM_TOTAL);

    k_prep<<<XB + WB, 256>>>((const float4*)x, (const float4*)wp, (const float4*)wn);
    plinear_gemm<<<M_TILES * N_TILES, 512, SMEM_TOTAL>>>(out);
}

// round 7
// speedup vs baseline: 1.1177x; 1.0687x over previous
#include <cuda_runtime.h>
#include <cuda_fp16.h>
#include <cstdint>
#include <cstddef>

// ============================================================
// out[16384,4096] = X[16384,4096] @ W[4096,4096]^T
// W = (w_pos>0) - (w_neg>0)  in {-1,0,+1}  (exact in fp16)
// CTA 128x128xK64, 8 warps (2x4), warp tile 64x32, 3-stage cp.async,
// 96KB smem -> 2 CTAs/SM (barrier stalls covered by co-resident CTA).
// ============================================================
#define M_TOTAL 16384
#define N_TOTAL 4096
#define K_TOTAL 4096

#define TILE_M 128
#define TILE_N 128
#define TILE_K 64
#define STAGES 3
#define NCHUNK (K_TOTAL / TILE_K)         // 64
#define N_TILES (N_TOTAL / TILE_N)        // 32
#define M_TILES (M_TOTAL / TILE_M)        // 128

#define A_BYTES (TILE_M * TILE_K * 2)     // 16384
#define B_BYTES (TILE_N * TILE_K * 2)     // 16384
#define STAGE_BYTES (A_BYTES + B_BYTES)   // 32768
#define SMEM_TOTAL (STAGES * STAGE_BYTES) // 98304

__device__ __align__(128) __half g_W[(size_t)N_TOTAL * K_TOTAL];  // [N,K] 32 MB
__device__ __align__(128) __half g_X[(size_t)M_TOTAL * K_TOTAL];  // [M,K] 128 MB

// ============================================================
// Base-ISA PTX helpers
// ============================================================
__device__ __forceinline__ uint32_t smem_u32(const void* p) {
    uint32_t a;
    asm("{ .reg .u64 t; cvta.to.shared.u64 t, %1; cvt.u32.u64 %0, t; }"
        : "=r"(a) : "l"(p));
    return a;
}

#define CP_ASYNC16(dst_u32, src_ptr) \
    asm volatile("cp.async.cg.shared.global [%0], [%1], 16;" \
                 :: "r"(dst_u32), "l"(src_ptr) : "memory")
#define CP_COMMIT() asm volatile("cp.async.commit_group;" ::: "memory")
#define CP_WAIT(n)  asm volatile("cp.async.wait_group %0;" :: "n"(n) : "memory")

__device__ __forceinline__ void ldsm4(uint32_t* r, uint32_t addr) {
    asm volatile("ldmatrix.sync.aligned.m8n8.x4.shared.b16 {%0,%1,%2,%3}, [%4];"
                 : "=r"(r[0]), "=r"(r[1]), "=r"(r[2]), "=r"(r[3]) : "r"(addr));
}

__device__ __forceinline__ void mma16816(float* d, const uint32_t* a,
                                         uint32_t b0, uint32_t b1) {
    asm volatile(
        "mma.sync.aligned.m16n8k16.row.col.f32.f16.f16.f32 "
        "{%0,%1,%2,%3}, {%4,%5,%6,%7}, {%8,%9}, {%0,%1,%2,%3};"
        : "+f"(d[0]), "+f"(d[1]), "+f"(d[2]), "+f"(d[3])
        : "r"(a[0]), "r"(a[1]), "r"(a[2]), "r"(a[3]), "r"(b0), "r"(b1));
}

__device__ __forceinline__ uint32_t sw128(uint32_t off) {
    return off ^ ((off >> 3) & 0x70u);
}

// ============================================================
// Merged prep kernel
// ============================================================
#define N4X ((M_TOTAL * K_TOTAL) / 4)     // 16777216
#define N4W ((N_TOTAL * K_TOTAL) / 4)     // 4194304
#define XB  (N4X / 256)
#define WB  (N4W / 256)

__global__ void k_prep(const float4* __restrict__ x,
                       const float4* __restrict__ wp,
                       const float4* __restrict__ wn) {
    int i = blockIdx.x * 256 + threadIdx.x;
    if (i < N4X) {
        float4 v = x[i];
        __half2* dst = (__half2*)g_X;
        dst[2 * i + 0] = __floats2half2_rn(v.x, v.y);
        dst[2 * i + 1] = __floats2half2_rn(v.z, v.w);
    } else {
        int j = i - N4X;
        float4 p = wp[j];
        float4 n = wn[j];
        float a = (float)((p.x > 0.f) - (n.x > 0.f));
        float b = (float)((p.y > 0.f) - (n.y > 0.f));
        float c = (float)((p.z > 0.f) - (n.z > 0.f));
        float d = (float)((p.w > 0.f) - (n.w > 0.f));
        __half2* dst = (__half2*)g_W;
        dst[2 * j + 0] = __floats2half2_rn(a, b);
        dst[2 * j + 1] = __floats2half2_rn(c, d);
    }
}

// ============================================================
// GEMM
// ============================================================
// Stage fill with 256 threads: A + B each 128 rows x 128B.
// Thread t -> row t>>1, 4 x 16B at col (t&1)*64, for both A and B.
__device__ __forceinline__ void issue_tile_loads(
    uint32_t smem_base, int s, int kc, int m0, int n0, int tid)
{
    uint32_t sa = smem_base + (uint32_t)s * STAGE_BYTES;
    uint32_t sb = sa + A_BYTES;
    const int row = tid >> 1;
    const int c0  = (tid & 1) * 4;
    const char* srcA = (const char*)(g_X + (size_t)(m0 + row) * K_TOTAL + kc * TILE_K);
    const char* srcB = (const char*)(g_W + (size_t)(n0 + row) * K_TOTAL + kc * TILE_K);
    uint32_t rb = (uint32_t)row * 128u;
    #pragma unroll
    for (int c = 0; c < 4; c++) {
        uint32_t off = rb + (uint32_t)(c0 + c) * 16u;
        uint32_t sw = sw128(off);
        CP_ASYNC16(sa + sw, srcA + (c0 + c) * 16);
        CP_ASYNC16(sb + sw, srcB + (c0 + c) * 16);
    }
}

__global__ void __launch_bounds__(256, 2) plinear_gemm(float* __restrict__ out) {
    extern __shared__ char smem[];
    uint32_t smem_base = smem_u32(smem);
    const int tid = threadIdx.x;
    const int wid = tid >> 5;
    const int lid = tid & 31;

    // N-fast: wave shares X tiles, W stays L2-resident
    const int nt = blockIdx.x & (N_TILES - 1);
    const int mt = blockIdx.x >> 5;
    const int m0 = mt * TILE_M;
    const int n0 = nt * TILE_N;

    // warp grid 2(M) x 4(N): warp tile 64 x 32
    const int mwarp = (wid >> 2) * 64;
    const int nwarp = (wid & 3) * 32;

    float acc[4][4][4];
    #pragma unroll
    for (int i = 0; i < 4; i++)
        #pragma unroll
        for (int j = 0; j < 4; j++)
            #pragma unroll
            for (int c = 0; c < 4; c++) acc[i][j][c] = 0.f;

    // Pre-swizzled ldmatrix base offsets; k-step advance by XOR (col bits 5-6
    // of the pre-swizzle offset are zero -> sw128(off+kb) == sw128(off)^kb).
    const int a_r = (lid & 7) + (((lid >> 3) & 1) << 3);
    const int a_c = (lid >> 4) << 4;
    const int b_r = (lid & 7) + ((lid >> 4) << 3);
    const int b_c = ((lid >> 3) & 1) << 4;
    uint32_t aoff[4], boff[2];
    #pragma unroll
    for (int i = 0; i < 4; i++)
        aoff[i] = sw128((uint32_t)(mwarp + i * 16 + a_r) * 128u + a_c);
    #pragma unroll
    for (int j = 0; j < 2; j++)
        boff[j] = sw128((uint32_t)(nwarp + j * 16 + b_r) * 128u + b_c) + A_BYTES;

    // Prologue: stages 0..1 (prefetch distance 2)
    issue_tile_loads(smem_base, 0, 0, m0, n0, tid); CP_COMMIT();
    issue_tile_loads(smem_base, 1, 1, m0, n0, tid); CP_COMMIT();

    uint32_t a[2][4][4], b[2][2][4];
    int s_cur = 0;

    #pragma unroll 1
    for (int kc = 0; kc < NCHUNK; kc++) {
        CP_WAIT(1);          // stage kc arrived (group kc+1 may be pending)
        __syncthreads();     // + stage kc-1 reads complete (prev iter)

        const int pf = kc + 2;
        if (pf < NCHUNK) {
            int sp = s_cur + 2; if (sp >= STAGES) sp -= STAGES;
            issue_tile_loads(smem_base, sp, pf, m0, n0, tid);
        }
        CP_COMMIT();

        const uint32_t sa = smem_base + (uint32_t)s_cur * STAGE_BYTES;
        if (++s_cur == STAGES) s_cur = 0;

        // k-step 0 fragments
        #pragma unroll
        for (int i = 0; i < 4; i++) ldsm4(a[0][i], sa + aoff[i]);
        #pragma unroll
        for (int j = 0; j < 2; j++) ldsm4(b[0][j], sa + boff[j]);

        #pragma unroll
        for (int ks = 0; ks < 4; ks++) {
            const int cur = ks & 1, nxt = cur ^ 1;
            if (ks < 3) {
                const uint32_t kb = (uint32_t)(ks + 1) * 32u;  // bits 5-6 only
                #pragma unroll
                for (int i = 0; i < 4; i++) ldsm4(a[nxt][i], sa + (aoff[i] ^ kb));
                #pragma unroll
                for (int j = 0; j < 2; j++) ldsm4(b[nxt][j], sa + (boff[j] ^ kb));
            }
            #pragma unroll
            for (int i = 0; i < 4; i++)
                #pragma unroll
                for (int j = 0; j < 2; j++) {
                    mma16816(acc[i][2 * j + 0], a[cur][i], b[cur][j][0], b[cur][j][1]);
                    mma16816(acc[i][2 * j + 1], a[cur][i], b[cur][j][2], b[cur][j][3]);
                }
        }
    }

    // Epilogue
    {
        const int g  = lid >> 2;
        const int t2 = (lid & 3) * 2;
        #pragma unroll
        for (int i = 0; i < 4; i++) {
            float* r0 = out + (size_t)(m0 + mwarp + i * 16 + g) * N_TOTAL + n0 + nwarp + t2;
            float* r1 = r0 + 8 * N_TOTAL;
            #pragma unroll
            for (int j = 0; j < 4; j++) {
                *(float2*)(r0 + j * 8) = make_float2(acc[i][j][0], acc[i][j][1]);
                *(float2*)(r1 + j * 8) = make_float2(acc[i][j][2], acc[i][j][3]);
            }
        }
    }
}

// ============================================================
// Launch
// ============================================================
extern "C" void kernel_launch(void* const* d_in, const int* in_sizes, int n_in,
                              void* d_out, int out_size) {
    const float* x  = (const float*)d_in[0];
    const float* wp = (const float*)d_in[1];
    const float* wn = (const float*)d_in[2];
    float* out = (float*)d_out;

    cudaFuncSetAttribute(plinear_gemm,
                         cudaFuncAttributeMaxDynamicSharedMemorySize, SMEM_TOTAL);

    k_prep<<<XB + WB, 256>>>((const float4*)x, (const float4*)wp, (const float4*)wn);
    plinear_gemm<<<M_TILES * N_TILES, 256, SMEM_TOTAL>>>(out);
}